// round 7
// baseline (speedup 1.0000x reference)
#include <cuda_runtime.h>
#include <cuda_bf16.h>

// LogSumExpPooling2D: x [8,256,256,64] f32 NHWC -> out [1,128,128,64]
// out[ho,wo,c] = (1/100) * log( sum_{n,dh,dw} exp(100 * x[n,2ho+dh,2wo+dw,c]) )
//
// R7: R6 math (fused ex2/lg2 LSE, shared-max across dw lane pair) made
// PERSISTENT: grid = 1024 CTAs (single wave at ~7 CTAs/SM), each 128-thread
// block loops over 4 pixel-groups (4 warps x 4 iters = 16 pixels/block).
// Removes 3+ wave transitions / CTA prologue replays so the LDG queue never
// drains between pixel batches.

#define K2F       144.2695040889f     // 100 / ln(2)
#define LN2_D100  0.0069314718056f    // ln(2) / 100

#define NBLK   1024
#define ITERS  4                       // 1024 blk * 4 warps * 4 iters = 16384 pixels

__device__ __forceinline__ float ex2(float t) {
    float r;
    asm("ex2.approx.ftz.f32 %0, %1;" : "=f"(r) : "f"(t));
    return r;
}
__device__ __forceinline__ float lg2(float t) {
    float r;
    asm("lg2.approx.ftz.f32 %0, %1;" : "=f"(r) : "f"(t));
    return r;
}

__global__ __launch_bounds__(128)
void lse_pool_kernel(const float* __restrict__ x, float* __restrict__ out)
{
    const int lane = threadIdx.x & 31;
    const int dw   = lane >> 4;   // 0: even w pixel, 1: odd w pixel
    const int j    = lane & 15;   // float4 index within 64 channels

    // First pixel for this warp; stride NBLK*4 warps per iteration.
    int pixel = blockIdx.x * 4 + (threadIdx.x >> 5);

#pragma unroll
    for (int it = 0; it < ITERS; ++it, pixel += NBLK * 4) {
        const int wo = pixel & 127;
        const int ho = pixel >> 7;

        // float4 strides: w -> 16, h -> 4096, n -> 1048576
        const float4* __restrict__ xb = reinterpret_cast<const float4*>(x)
            + ((size_t)(2 * ho) * 4096 + (size_t)(2 * wo + dw) * 16 + (size_t)j);

        // Front-batched loads: 16 independent LDG.128 in flight per thread.
        float4 v[16];
#pragma unroll
        for (int n = 0; n < 8; ++n) {
#pragma unroll
            for (int dh = 0; dh < 2; ++dh) {
                v[n * 2 + dh] = xb[(size_t)n * 1048576 + (size_t)dh * 4096];
            }
        }

        // Per-channel max over the 16 local values.
        float4 m = v[0];
#pragma unroll
        for (int i = 1; i < 16; ++i) {
            m.x = fmaxf(m.x, v[i].x);
            m.y = fmaxf(m.y, v[i].y);
            m.z = fmaxf(m.z, v[i].z);
            m.w = fmaxf(m.w, v[i].w);
        }
        // Share max across the dw lane-pair.
        m.x = fmaxf(m.x, __shfl_xor_sync(0xffffffffu, m.x, 16));
        m.y = fmaxf(m.y, __shfl_xor_sync(0xffffffffu, m.y, 16));
        m.z = fmaxf(m.z, __shfl_xor_sync(0xffffffffu, m.z, 16));
        m.w = fmaxf(m.w, __shfl_xor_sync(0xffffffffu, m.w, 16));

        // exp(100(v-m)) = ex2(K2*v + nk), nk = -K2*m.
        float4 nk;
        nk.x = -K2F * m.x;
        nk.y = -K2F * m.y;
        nk.z = -K2F * m.z;
        nk.w = -K2F * m.w;

        float4 s = make_float4(0.f, 0.f, 0.f, 0.f);
#pragma unroll
        for (int i = 0; i < 16; ++i) {
            s.x += ex2(fmaf(K2F, v[i].x, nk.x));
            s.y += ex2(fmaf(K2F, v[i].y, nk.y));
            s.z += ex2(fmaf(K2F, v[i].z, nk.z));
            s.w += ex2(fmaf(K2F, v[i].w, nk.w));
        }
        // Merge the two w-halves (same max -> plain add).
        s.x += __shfl_xor_sync(0xffffffffu, s.x, 16);
        s.y += __shfl_xor_sync(0xffffffffu, s.y, 16);
        s.z += __shfl_xor_sync(0xffffffffu, s.z, 16);
        s.w += __shfl_xor_sync(0xffffffffu, s.w, 16);

        if (dw == 0) {
            float4 o;
            o.x = fmaf(lg2(s.x), LN2_D100, m.x);
            o.y = fmaf(lg2(s.y), LN2_D100, m.y);
            o.z = fmaf(lg2(s.z), LN2_D100, m.z);
            o.w = fmaf(lg2(s.w), LN2_D100, m.w);
            reinterpret_cast<float4*>(out)[(size_t)pixel * 16 + j] = o;
        }
    }
}

extern "C" void kernel_launch(void* const* d_in, const int* in_sizes, int n_in,
                              void* d_out, int out_size)
{
    const float* x = (const float*)d_in[0];
    float* out = (float*)d_out;
    // Persistent single-wave launch: 1024 blocks x 128 threads, 4 iters each.
    lse_pool_kernel<<<NBLK, 128>>>(x, out);
}

// round 8
// speedup vs baseline: 1.0721x; 1.0721x over previous
#include <cuda_runtime.h>
#include <cuda_bf16.h>

// LogSumExpPooling2D: x [8,256,256,64] f32 NHWC -> out [1,128,128,64]
// out[ho,wo,c] = (1/100) * log( sum_{n,dh,dw} exp(100 * x[n,2ho+dh,2wo+dw,c]) )
//
// R8: R6 (best: 1 warp/pixel, lanes split dw, 16 front-batched coalesced
// LDG.128/thread, fused ex2/lg2 LSE, block=128 grid=4096) + STREAMING cache
// policy: ld.global.cs for the read-once input stream, st.global.cs for the
// output. Evict-first lines shorten L2 victim handling on a pure stream.

#define K2F       144.2695040889f     // 100 / ln(2)
#define LN2_D100  0.0069314718056f    // ln(2) / 100

__device__ __forceinline__ float ex2(float t) {
    float r;
    asm("ex2.approx.ftz.f32 %0, %1;" : "=f"(r) : "f"(t));
    return r;
}
__device__ __forceinline__ float lg2(float t) {
    float r;
    asm("lg2.approx.ftz.f32 %0, %1;" : "=f"(r) : "f"(t));
    return r;
}

__global__ __launch_bounds__(128)
void lse_pool_kernel(const float* __restrict__ x, float* __restrict__ out)
{
    const int warp = (blockIdx.x * 128 + threadIdx.x) >> 5;  // 0..16383
    const int lane = threadIdx.x & 31;
    const int wo   = warp & 127;
    const int ho   = warp >> 7;
    const int dw   = lane >> 4;   // 0: even w pixel, 1: odd w pixel
    const int j    = lane & 15;   // float4 index within 64 channels

    // float4 strides: w -> 16, h -> 4096, n -> 1048576
    const float4* __restrict__ xb = reinterpret_cast<const float4*>(x)
        + ((size_t)(2 * ho) * 4096 + (size_t)(2 * wo + dw) * 16 + (size_t)j);

    // Front-batched streaming loads: 16 independent LDG.128.CS per thread.
    float4 v[16];
#pragma unroll
    for (int n = 0; n < 8; ++n) {
#pragma unroll
        for (int dh = 0; dh < 2; ++dh) {
            v[n * 2 + dh] = __ldcs(xb + (size_t)n * 1048576 + (size_t)dh * 4096);
        }
    }

    // Per-channel max over the 16 local values.
    float4 m = v[0];
#pragma unroll
    for (int i = 1; i < 16; ++i) {
        m.x = fmaxf(m.x, v[i].x);
        m.y = fmaxf(m.y, v[i].y);
        m.z = fmaxf(m.z, v[i].z);
        m.w = fmaxf(m.w, v[i].w);
    }
    // Share max across the dw lane-pair so both halves use the same reference.
    m.x = fmaxf(m.x, __shfl_xor_sync(0xffffffffu, m.x, 16));
    m.y = fmaxf(m.y, __shfl_xor_sync(0xffffffffu, m.y, 16));
    m.z = fmaxf(m.z, __shfl_xor_sync(0xffffffffu, m.z, 16));
    m.w = fmaxf(m.w, __shfl_xor_sync(0xffffffffu, m.w, 16));

    // exp(100(v-m)) = ex2(K2*v + nk), nk = -K2*m.
    float4 nk;
    nk.x = -K2F * m.x;
    nk.y = -K2F * m.y;
    nk.z = -K2F * m.z;
    nk.w = -K2F * m.w;

    // Sum of ex2(K2*v - K2*m): one FFMA + one EX2 per value.
    float4 s = make_float4(0.f, 0.f, 0.f, 0.f);
#pragma unroll
    for (int i = 0; i < 16; ++i) {
        s.x += ex2(fmaf(K2F, v[i].x, nk.x));
        s.y += ex2(fmaf(K2F, v[i].y, nk.y));
        s.z += ex2(fmaf(K2F, v[i].z, nk.z));
        s.w += ex2(fmaf(K2F, v[i].w, nk.w));
    }
    // Merge the two w-halves (same max -> plain add).
    s.x += __shfl_xor_sync(0xffffffffu, s.x, 16);
    s.y += __shfl_xor_sync(0xffffffffu, s.y, 16);
    s.z += __shfl_xor_sync(0xffffffffu, s.z, 16);
    s.w += __shfl_xor_sync(0xffffffffu, s.w, 16);

    if (dw == 0) {
        float4 o;
        o.x = fmaf(lg2(s.x), LN2_D100, m.x);
        o.y = fmaf(lg2(s.y), LN2_D100, m.y);
        o.z = fmaf(lg2(s.z), LN2_D100, m.z);
        o.w = fmaf(lg2(s.w), LN2_D100, m.w);
        __stcs(reinterpret_cast<float4*>(out) + (size_t)(ho * 128 + wo) * 16 + j, o);
    }
}

extern "C" void kernel_launch(void* const* d_in, const int* in_sizes, int n_in,
                              void* d_out, int out_size)
{
    const float* x = (const float*)d_in[0];
    float* out = (float*)d_out;
    // 16384 output pixels, 1 warp each, 4 warps per 128-thread block.
    lse_pool_kernel<<<4096, 128>>>(x, out);
}

// round 9
// speedup vs baseline: 1.1794x; 1.1001x over previous
#include <cuda_runtime.h>
#include <cuda_bf16.h>

// LogSumExpPooling2D: x [8,256,256,64] f32 NHWC -> out [1,128,128,64]
// out[ho,wo,c] = (1/100) * log( sum_{n,dh,dw} exp(100 * x[n,2ho+dh,2wo+dw,c]) )
//
// R9: identical per-warp structure to R8 (1 warp/pixel, lanes split dw,
// 16 front-batched coalesced LDG.128.CS/thread, fused ex2/lg2 LSE, .cs store)
// with block=64 / grid=8192: finer CTA granularity for smoother per-SM
// phase interleaving and a finer final-wave tail.

#define K2F       144.2695040889f     // 100 / ln(2)
#define LN2_D100  0.0069314718056f    // ln(2) / 100

__device__ __forceinline__ float ex2(float t) {
    float r;
    asm("ex2.approx.ftz.f32 %0, %1;" : "=f"(r) : "f"(t));
    return r;
}
__device__ __forceinline__ float lg2(float t) {
    float r;
    asm("lg2.approx.ftz.f32 %0, %1;" : "=f"(r) : "f"(t));
    return r;
}

__global__ __launch_bounds__(64)
void lse_pool_kernel(const float* __restrict__ x, float* __restrict__ out)
{
    const int warp = (blockIdx.x * 64 + threadIdx.x) >> 5;   // 0..16383
    const int lane = threadIdx.x & 31;
    const int wo   = warp & 127;
    const int ho   = warp >> 7;
    const int dw   = lane >> 4;   // 0: even w pixel, 1: odd w pixel
    const int j    = lane & 15;   // float4 index within 64 channels

    // float4 strides: w -> 16, h -> 4096, n -> 1048576
    const float4* __restrict__ xb = reinterpret_cast<const float4*>(x)
        + ((size_t)(2 * ho) * 4096 + (size_t)(2 * wo + dw) * 16 + (size_t)j);

    // Front-batched streaming loads: 16 independent LDG.128.CS per thread.
    float4 v[16];
#pragma unroll
    for (int n = 0; n < 8; ++n) {
#pragma unroll
        for (int dh = 0; dh < 2; ++dh) {
            v[n * 2 + dh] = __ldcs(xb + (size_t)n * 1048576 + (size_t)dh * 4096);
        }
    }

    // Per-channel max over the 16 local values.
    float4 m = v[0];
#pragma unroll
    for (int i = 1; i < 16; ++i) {
        m.x = fmaxf(m.x, v[i].x);
        m.y = fmaxf(m.y, v[i].y);
        m.z = fmaxf(m.z, v[i].z);
        m.w = fmaxf(m.w, v[i].w);
    }
    // Share max across the dw lane-pair so both halves use the same reference.
    m.x = fmaxf(m.x, __shfl_xor_sync(0xffffffffu, m.x, 16));
    m.y = fmaxf(m.y, __shfl_xor_sync(0xffffffffu, m.y, 16));
    m.z = fmaxf(m.z, __shfl_xor_sync(0xffffffffu, m.z, 16));
    m.w = fmaxf(m.w, __shfl_xor_sync(0xffffffffu, m.w, 16));

    // exp(100(v-m)) = ex2(K2*v + nk), nk = -K2*m.
    float4 nk;
    nk.x = -K2F * m.x;
    nk.y = -K2F * m.y;
    nk.z = -K2F * m.z;
    nk.w = -K2F * m.w;

    // Sum of ex2(K2*v - K2*m): one FFMA + one EX2 per value.
    float4 s = make_float4(0.f, 0.f, 0.f, 0.f);
#pragma unroll
    for (int i = 0; i < 16; ++i) {
        s.x += ex2(fmaf(K2F, v[i].x, nk.x));
        s.y += ex2(fmaf(K2F, v[i].y, nk.y));
        s.z += ex2(fmaf(K2F, v[i].z, nk.z));
        s.w += ex2(fmaf(K2F, v[i].w, nk.w));
    }
    // Merge the two w-halves (same max -> plain add).
    s.x += __shfl_xor_sync(0xffffffffu, s.x, 16);
    s.y += __shfl_xor_sync(0xffffffffu, s.y, 16);
    s.z += __shfl_xor_sync(0xffffffffu, s.z, 16);
    s.w += __shfl_xor_sync(0xffffffffu, s.w, 16);

    if (dw == 0) {
        float4 o;
        o.x = fmaf(lg2(s.x), LN2_D100, m.x);
        o.y = fmaf(lg2(s.y), LN2_D100, m.y);
        o.z = fmaf(lg2(s.z), LN2_D100, m.z);
        o.w = fmaf(lg2(s.w), LN2_D100, m.w);
        __stcs(reinterpret_cast<float4*>(out) + (size_t)(ho * 128 + wo) * 16 + j, o);
    }
}

extern "C" void kernel_launch(void* const* d_in, const int* in_sizes, int n_in,
                              void* d_out, int out_size)
{
    const float* x = (const float*)d_in[0];
    float* out = (float*)d_out;
    // 16384 output pixels, 1 warp each, 2 warps per 64-thread block.
    lse_pool_kernel<<<8192, 64>>>(x, out);
}